// round 5
// baseline (speedup 1.0000x reference)
#include <cuda_runtime.h>

// BoundaryAwareBCELoss — fused 3x3 binary morphology boundary + weighted BCE mean.
// R5: binary-sum boundary test. target ∈ {0,1} ⇒ 3x3 window non-uniform
// ⟺ window-sum s ∈ (0,9) (exact in fp32). Separable running sums replace the
// dual min/max stencil: 2+2 FADD/px, 2 shuffles/row, 1 halo register.
// Warp-private 128-col segments, rolling vertical window, no smem/barriers in
// the main loop, fused threadfence final reduction (single launch).

#define IMG_W 1024
#define IMG_H 1024
#define IMG_B 32
#define RPB   32
#define GX    (IMG_H / RPB)          // 32
#define NBLK  (GX * IMG_B)           // 1024
#define NPIXD ((double)IMG_B * IMG_H * IMG_W)

__device__ float g_partial[NBLK];
__device__ unsigned int g_count;     // zero at module load; reset each call

__global__ __launch_bounds__(256) void babce_kernel(
    const float* __restrict__ pred, const float* __restrict__ target,
    float* __restrict__ out)
{
    __shared__ float  s_warp[8];
    __shared__ double s_dwarp[8];
    __shared__ bool   s_last;

    const int tid  = threadIdx.x;
    const int lane = tid & 31;
    const int wid  = tid >> 5;
    const int y0   = blockIdx.x * RPB;
    const int b    = blockIdx.y;

    const int c0 = wid * 128;                 // warp column base
    const int x0 = c0 + lane * 4;             // this thread's 4 columns
    const bool is_edge = (lane == 0) || (lane == 31);
    // halo column (clamped duplication preserves the value-support of the
    // window, so the sum test stays exact at image borders)
    const int hcol = (lane == 0) ? ((c0 > 0) ? c0 - 1 : 0)
                                 : ((c0 + 128 < IMG_W) ? c0 + 128 : IMG_W - 1);

    const float* __restrict__ timg = target + (size_t)b * IMG_H * IMG_W;
    const float* __restrict__ pimg = pred   + (size_t)b * IMG_H * IMG_W;

    const int yu = (y0 > 0) ? y0 - 1 : 0;
    float4 tu = *(const float4*)(timg + (size_t)yu * IMG_W + x0);
    float4 tm = *(const float4*)(timg + (size_t)y0 * IMG_W + x0);
    float hu = 0.f, hm = 0.f;
    if (is_edge) {
        hu = timg[(size_t)yu * IMG_W + hcol];
        hm = timg[(size_t)y0 * IMG_W + hcol];
    }

    float sum = 0.0f;

    #pragma unroll 4
    for (int r = 0; r < RPB; r++) {
        const int y  = y0 + r;
        const int yd = (y < IMG_H - 1) ? y + 1 : y;
        const float4 td = *(const float4*)(timg + (size_t)yd * IMG_W + x0);
        const float4 pp = *(const float4*)(pimg + (size_t)y  * IMG_W + x0);
        float hd = 0.f;
        if (is_edge) hd = timg[(size_t)yd * IMG_W + hcol];

        // vertical running sums (exact: values are 0.0 / 1.0)
        float4 vs;
        vs.x = tu.x + tm.x + td.x;
        vs.y = tu.y + tm.y + td.y;
        vs.z = tu.z + tm.z + td.z;
        vs.w = tu.w + tm.w + td.w;
        const float hvs = hu + hm + hd;

        // neighbor column sums across lanes
        float ls = __shfl_up_sync  (0xFFFFFFFFu, vs.w, 1);
        float rs = __shfl_down_sync(0xFFFFFFFFu, vs.x, 1);
        if (lane == 0)  ls = hvs;
        if (lane == 31) rs = hvs;

        // horizontal 3-tap sums -> boundary flag -> weighted BCE
        const float s0 = ls   + vs.x + vs.y;
        const float s1 = vs.x + vs.y + vs.z;
        const float s2 = vs.y + vs.z + vs.w;
        const float s3 = vs.z + vs.w + rs;

        float arg, w;
        arg = (tm.x > 0.5f) ? pp.x : (1.0f - pp.x);
        w   = (s0 > 0.5f && s0 < 8.5f) ? 3.0f : 1.0f;
        sum = fmaf(w, -__logf(arg), sum);

        arg = (tm.y > 0.5f) ? pp.y : (1.0f - pp.y);
        w   = (s1 > 0.5f && s1 < 8.5f) ? 3.0f : 1.0f;
        sum = fmaf(w, -__logf(arg), sum);

        arg = (tm.z > 0.5f) ? pp.z : (1.0f - pp.z);
        w   = (s2 > 0.5f && s2 < 8.5f) ? 3.0f : 1.0f;
        sum = fmaf(w, -__logf(arg), sum);

        arg = (tm.w > 0.5f) ? pp.w : (1.0f - pp.w);
        w   = (s3 > 0.5f && s3 < 8.5f) ? 3.0f : 1.0f;
        sum = fmaf(w, -__logf(arg), sum);

        tu = tm;  tm = td;
        hu = hm;  hm = hd;
    }

    // ---- block reduction (fp32) ----
    #pragma unroll
    for (int off = 16; off > 0; off >>= 1)
        sum += __shfl_xor_sync(0xFFFFFFFFu, sum, off);
    if (lane == 0) s_warp[wid] = sum;
    __syncthreads();

    if (tid == 0) {
        float v = 0.0f;
        #pragma unroll
        for (int i = 0; i < 8; i++) v += s_warp[i];
        g_partial[blockIdx.y * gridDim.x + blockIdx.x] = v;
        __threadfence();
        const unsigned done = atomicAdd(&g_count, 1u);
        s_last = (done == NBLK - 1);
    }
    __syncthreads();

    // ---- last block: final fp64 reduction, reset counter ----
    if (s_last) {
        __threadfence();
        double v = (double)g_partial[tid]
                 + (double)g_partial[tid + 256]
                 + (double)g_partial[tid + 512]
                 + (double)g_partial[tid + 768];
        #pragma unroll
        for (int off = 16; off > 0; off >>= 1)
            v += __shfl_xor_sync(0xFFFFFFFFu, v, off);
        if (lane == 0) s_dwarp[wid] = v;
        __syncthreads();
        if (tid == 0) {
            double t = 0.0;
            #pragma unroll
            for (int i = 0; i < 8; i++) t += s_dwarp[i];
            out[0] = (float)(t / NPIXD);
            g_count = 0;   // restore for next graph replay (deterministic)
        }
    }
}

extern "C" void kernel_launch(void* const* d_in, const int* in_sizes, int n_in,
                              void* d_out, int out_size)
{
    const float* pred   = (const float*)d_in[0];
    const float* target = (const float*)d_in[1];
    float* out = (float*)d_out;

    dim3 grid(GX, IMG_B);   // (32, 32) = 1024 blocks
    babce_kernel<<<grid, 256>>>(pred, target, out);
}

// round 6
// speedup vs baseline: 1.1907x; 1.1907x over previous
#include <cuda_runtime.h>

// BoundaryAwareBCELoss — fused 3x3 binary morphology boundary + weighted BCE mean.
// R6: persistent grid (148 SMs × 5 blocks, all resident, zero waves) with
// static round-robin strip assignment (deterministic). RPB=16 strips, binary
// window-sum boundary test, register accumulation across strips, single block
// reduction at exit, fused threadfence final reduction (single launch).

#define IMG_W  1024
#define IMG_H  1024
#define IMG_B  32
#define RPB    16
#define SPI    (IMG_H / RPB)            // 64 strips per image
#define NSTRIP (SPI * IMG_B)            // 2048 strips
#define GRID   740                      // 148 SMs * 5 blocks
#define NPIXD  ((double)IMG_B * IMG_H * IMG_W)

__device__ float g_partial[GRID];
__device__ unsigned int g_count;        // zero at load; reset by last block

__global__ __launch_bounds__(256, 5) void babce_kernel(
    const float* __restrict__ pred, const float* __restrict__ target,
    float* __restrict__ out)
{
    __shared__ float  s_warp[8];
    __shared__ double s_dwarp[8];
    __shared__ bool   s_last;

    const int tid  = threadIdx.x;
    const int lane = tid & 31;
    const int wid  = tid >> 5;

    const int c0 = wid * 128;                 // warp column base
    const int x0 = c0 + lane * 4;             // this thread's 4 columns
    const bool is_edge = (lane == 0) || (lane == 31);
    // clamped halo column: duplication preserves window value-support,
    // so the binary-sum boundary test stays exact at image borders
    const int hcol = (lane == 0) ? ((c0 > 0) ? c0 - 1 : 0)
                                 : ((c0 + 128 < IMG_W) ? c0 + 128 : IMG_W - 1);

    float sum = 0.0f;   // thread-local across all assigned strips

    for (int sid = blockIdx.x; sid < NSTRIP; sid += GRID) {
        const int b  = sid >> 6;              // sid / SPI
        const int y0 = (sid & (SPI - 1)) * RPB;

        const float* __restrict__ timg = target + (size_t)b * IMG_H * IMG_W;
        const float* __restrict__ pimg = pred   + (size_t)b * IMG_H * IMG_W;

        const int yu = (y0 > 0) ? y0 - 1 : 0;
        float4 tu = *(const float4*)(timg + (size_t)yu * IMG_W + x0);
        float4 tm = *(const float4*)(timg + (size_t)y0 * IMG_W + x0);
        float hu = 0.f, hm = 0.f;
        if (is_edge) {
            hu = timg[(size_t)yu * IMG_W + hcol];
            hm = timg[(size_t)y0 * IMG_W + hcol];
        }

        #pragma unroll 4
        for (int r = 0; r < RPB; r++) {
            const int y  = y0 + r;
            const int yd = (y < IMG_H - 1) ? y + 1 : y;
            const float4 td = *(const float4*)(timg + (size_t)yd * IMG_W + x0);
            const float4 pp = *(const float4*)(pimg + (size_t)y  * IMG_W + x0);
            float hd = 0.f;
            if (is_edge) hd = timg[(size_t)yd * IMG_W + hcol];

            // vertical running sums (exact: values are 0.0 / 1.0)
            float4 vs;
            vs.x = tu.x + tm.x + td.x;
            vs.y = tu.y + tm.y + td.y;
            vs.z = tu.z + tm.z + td.z;
            vs.w = tu.w + tm.w + td.w;
            const float hvs = hu + hm + hd;

            // neighbor column sums across lanes
            float ls = __shfl_up_sync  (0xFFFFFFFFu, vs.w, 1);
            float rs = __shfl_down_sync(0xFFFFFFFFu, vs.x, 1);
            if (lane == 0)  ls = hvs;
            if (lane == 31) rs = hvs;

            // horizontal 3-tap sums -> boundary flag -> weighted BCE
            const float s0 = ls   + vs.x + vs.y;
            const float s1 = vs.x + vs.y + vs.z;
            const float s2 = vs.y + vs.z + vs.w;
            const float s3 = vs.z + vs.w + rs;

            float arg, w;
            arg = (tm.x > 0.5f) ? pp.x : (1.0f - pp.x);
            w   = (s0 > 0.5f && s0 < 8.5f) ? 3.0f : 1.0f;
            sum = fmaf(w, -__logf(arg), sum);

            arg = (tm.y > 0.5f) ? pp.y : (1.0f - pp.y);
            w   = (s1 > 0.5f && s1 < 8.5f) ? 3.0f : 1.0f;
            sum = fmaf(w, -__logf(arg), sum);

            arg = (tm.z > 0.5f) ? pp.z : (1.0f - pp.z);
            w   = (s2 > 0.5f && s2 < 8.5f) ? 3.0f : 1.0f;
            sum = fmaf(w, -__logf(arg), sum);

            arg = (tm.w > 0.5f) ? pp.w : (1.0f - pp.w);
            w   = (s3 > 0.5f && s3 < 8.5f) ? 3.0f : 1.0f;
            sum = fmaf(w, -__logf(arg), sum);

            tu = tm;  tm = td;
            hu = hm;  hm = hd;
        }
    }

    // ---- one block reduction at exit (fp32) ----
    #pragma unroll
    for (int off = 16; off > 0; off >>= 1)
        sum += __shfl_xor_sync(0xFFFFFFFFu, sum, off);
    if (lane == 0) s_warp[wid] = sum;
    __syncthreads();

    if (tid == 0) {
        float v = 0.0f;
        #pragma unroll
        for (int i = 0; i < 8; i++) v += s_warp[i];
        g_partial[blockIdx.x] = v;
        __threadfence();
        const unsigned done = atomicAdd(&g_count, 1u);
        s_last = (done == GRID - 1);
    }
    __syncthreads();

    // ---- last block: final fp64 reduction over 740 partials ----
    if (s_last) {
        __threadfence();
        double v = (double)g_partial[tid] + (double)g_partial[tid + 256];
        if (tid < GRID - 512) v += (double)g_partial[tid + 512];
        #pragma unroll
        for (int off = 16; off > 0; off >>= 1)
            v += __shfl_xor_sync(0xFFFFFFFFu, v, off);
        if (lane == 0) s_dwarp[wid] = v;
        __syncthreads();
        if (tid == 0) {
            double t = 0.0;
            #pragma unroll
            for (int i = 0; i < 8; i++) t += s_dwarp[i];
            out[0] = (float)(t / NPIXD);
            g_count = 0;   // restore for next graph replay (deterministic)
        }
    }
}

extern "C" void kernel_launch(void* const* d_in, const int* in_sizes, int n_in,
                              void* d_out, int out_size)
{
    const float* pred   = (const float*)d_in[0];
    const float* target = (const float*)d_in[1];
    float* out = (float*)d_out;

    babce_kernel<<<GRID, 256>>>(pred, target, out);
}

// round 7
// speedup vs baseline: 1.2419x; 1.0430x over previous
#include <cuda_runtime.h>

// BoundaryAwareBCELoss — fused 3x3 binary morphology boundary + weighted BCE mean.
// R7: contiguous per-image row partitions. grid = 32 images × 23 blocks = 736
// (all resident, 5 blocks/SM). Each block owns a 44/45-row range with ONE
// rolling vertical window => halo overhead 4.5% (was 12.5%) and 98.9% load
// balance (was 92%). Binary window-sum boundary test, shuffle horizontal
// combine, fused threadfence final reduction (single launch).

#define IMG_W  1024
#define IMG_H  1024
#define IMG_B  32
#define BPI    23                        // blocks per image
#define GRID   (IMG_B * BPI)             // 736 <= 740 resident capacity
#define NPIXD  ((double)IMG_B * IMG_H * IMG_W)

__device__ float g_partial[GRID];
__device__ unsigned int g_count;         // zero at load; reset by last block

__global__ __launch_bounds__(256, 5) void babce_kernel(
    const float* __restrict__ pred, const float* __restrict__ target,
    float* __restrict__ out)
{
    __shared__ float  s_warp[8];
    __shared__ double s_dwarp[8];
    __shared__ bool   s_last;

    const int tid  = threadIdx.x;
    const int lane = tid & 31;
    const int wid  = tid >> 5;

    const int b     = blockIdx.x / BPI;      // image
    const int chunk = blockIdx.x % BPI;      // row-range within image
    const int ys    = (chunk * IMG_H) / BPI;
    const int ye    = ((chunk + 1) * IMG_H) / BPI;   // 44 or 45 rows

    const int c0 = wid * 128;                 // warp column base
    const int x0 = c0 + lane * 4;             // this thread's 4 columns
    const bool is_edge = (lane == 0) || (lane == 31);
    // clamped halo column: duplication preserves window value-support,
    // so the binary-sum boundary test stays exact at image borders
    const int hcol = (lane == 0) ? ((c0 > 0) ? c0 - 1 : 0)
                                 : ((c0 + 128 < IMG_W) ? c0 + 128 : IMG_W - 1);

    const float* __restrict__ timg = target + (size_t)b * IMG_H * IMG_W;
    const float* __restrict__ pimg = pred   + (size_t)b * IMG_H * IMG_W;

    // rolling vertical window (clamped top halo)
    const int yu = (ys > 0) ? ys - 1 : 0;
    float4 tu = *(const float4*)(timg + (size_t)yu * IMG_W + x0);
    float4 tm = *(const float4*)(timg + (size_t)ys * IMG_W + x0);
    float hu = 0.f, hm = 0.f;
    if (is_edge) {
        hu = timg[(size_t)yu * IMG_W + hcol];
        hm = timg[(size_t)ys * IMG_W + hcol];
    }

    float sum = 0.0f;

    #pragma unroll 4
    for (int y = ys; y < ye; y++) {
        const int yd = (y < IMG_H - 1) ? y + 1 : y;
        const float4 td = *(const float4*)(timg + (size_t)yd * IMG_W + x0);
        const float4 pp = *(const float4*)(pimg + (size_t)y  * IMG_W + x0);
        float hd = 0.f;
        if (is_edge) hd = timg[(size_t)yd * IMG_W + hcol];

        // vertical running sums (exact: values are 0.0 / 1.0)
        float4 vs;
        vs.x = tu.x + tm.x + td.x;
        vs.y = tu.y + tm.y + td.y;
        vs.z = tu.z + tm.z + td.z;
        vs.w = tu.w + tm.w + td.w;
        const float hvs = hu + hm + hd;

        // neighbor column sums across lanes
        float ls = __shfl_up_sync  (0xFFFFFFFFu, vs.w, 1);
        float rs = __shfl_down_sync(0xFFFFFFFFu, vs.x, 1);
        if (lane == 0)  ls = hvs;
        if (lane == 31) rs = hvs;

        // horizontal 3-tap sums -> boundary flag -> weighted BCE
        const float s0 = ls   + vs.x + vs.y;
        const float s1 = vs.x + vs.y + vs.z;
        const float s2 = vs.y + vs.z + vs.w;
        const float s3 = vs.z + vs.w + rs;

        float arg, w;
        arg = (tm.x > 0.5f) ? pp.x : (1.0f - pp.x);
        w   = (s0 > 0.5f && s0 < 8.5f) ? 3.0f : 1.0f;
        sum = fmaf(w, -__logf(arg), sum);

        arg = (tm.y > 0.5f) ? pp.y : (1.0f - pp.y);
        w   = (s1 > 0.5f && s1 < 8.5f) ? 3.0f : 1.0f;
        sum = fmaf(w, -__logf(arg), sum);

        arg = (tm.z > 0.5f) ? pp.z : (1.0f - pp.z);
        w   = (s2 > 0.5f && s2 < 8.5f) ? 3.0f : 1.0f;
        sum = fmaf(w, -__logf(arg), sum);

        arg = (tm.w > 0.5f) ? pp.w : (1.0f - pp.w);
        w   = (s3 > 0.5f && s3 < 8.5f) ? 3.0f : 1.0f;
        sum = fmaf(w, -__logf(arg), sum);

        tu = tm;  tm = td;
        hu = hm;  hm = hd;
    }

    // ---- one block reduction at exit (fp32) ----
    #pragma unroll
    for (int off = 16; off > 0; off >>= 1)
        sum += __shfl_xor_sync(0xFFFFFFFFu, sum, off);
    if (lane == 0) s_warp[wid] = sum;
    __syncthreads();

    if (tid == 0) {
        float v = 0.0f;
        #pragma unroll
        for (int i = 0; i < 8; i++) v += s_warp[i];
        g_partial[blockIdx.x] = v;
        __threadfence();
        const unsigned done = atomicAdd(&g_count, 1u);
        s_last = (done == GRID - 1);
    }
    __syncthreads();

    // ---- last block: final fp64 reduction over 736 partials ----
    if (s_last) {
        __threadfence();
        double v = (double)g_partial[tid] + (double)g_partial[tid + 256];
        if (tid < GRID - 512) v += (double)g_partial[tid + 512];
        #pragma unroll
        for (int off = 16; off > 0; off >>= 1)
            v += __shfl_xor_sync(0xFFFFFFFFu, v, off);
        if (lane == 0) s_dwarp[wid] = v;
        __syncthreads();
        if (tid == 0) {
            double t = 0.0;
            #pragma unroll
            for (int i = 0; i < 8; i++) t += s_dwarp[i];
            out[0] = (float)(t / NPIXD);
            g_count = 0;   // restore for next graph replay (deterministic)
        }
    }
}

extern "C" void kernel_launch(void* const* d_in, const int* in_sizes, int n_in,
                              void* d_out, int out_size)
{
    const float* pred   = (const float*)d_in[0];
    const float* target = (const float*)d_in[1];
    float* out = (float*)d_out;

    babce_kernel<<<GRID, 256>>>(pred, target, out);
}